// round 10
// baseline (speedup 1.0000x reference)
#include <cuda_runtime.h>

#define SLICES 32
#define NCH 32            // 8 batches * {img,img_t} * {g,b}
#define NPIX 65536
#define NBIN 256

__device__ float g_pa[NCH][SLICES][NBIN];   // per-CTA sig0 partials (pure d=0 sums)
__device__ float g_pb[NCH][SLICES][NBIN];   // per-CTA fused 4096*N + sig(+1) partials

__device__ __forceinline__ float frcp(float x) {
    float y; asm("rcp.approx.f32 %0, %1;" : "=f"(y) : "f"(x)); return y;
}

#define E_P1 12.182493960703473f       // e^2.5

// sig(2.5f) linear model over f~U[0,1): mean A0, slope b0
#define A0_SIG 0.754354f
#define INV_B0 2.337788f               // 1 / 0.427755

// linear-fit tail compensation: sig(2.5(f-d)) ~= A + B*(f-1/2);  B_d = B_{1-d}
#define A_M1 0.9711630f    // mean of sig(2.5(f+1))      (d=-1)
#define ET2  0.0288370f    // mean of sig(2.5(f-2))      (d=+2)
#define ET3  0.0024650f    // mean of sig(2.5(f-3)); also deficiency at d=-2
#define ET4  0.0002030f    // mean of sig(2.5(f-4)); also deficiency at d=-3
#define B1   0.0639120f    // slope for d=-1 and d=+2
#define B2   0.0056371f    // slope for d=-2 and d=+3
#define B3   0.0004640f    // slope for d=-3 and d=+4

__device__ __forceinline__ void process_pixel(float x, float* s_a, float* s_b) {
    float u = x * 255.0f;
    int k = (int)u;                    // x < 1 -> k <= 254, f in [0,1)
    float f = u - (float)k;
    float e0 = __expf(-2.5f * f);      // e^{-2.5 f}

    atomicAdd(&s_a[k], frcp(1.0f + e0));                    // d=0 -> threshold k
    atomicAdd(&s_b[k], 4096.0f + frcp(1.0f + e0 * E_P1));   // count + d=+1 -> threshold k+1
}

__global__ __launch_bounds__(256) void hist_kernel(const float* __restrict__ img,
                                                   const float* __restrict__ img_t) {
    __shared__ float s_a[NBIN];
    __shared__ float s_b[NBIN];
    int t = threadIdx.x;
    s_a[t] = 0.0f;
    s_b[t] = 0.0f;
    __syncthreads();

    int cidx = blockIdx.y;                 // 0..31  (= b*4 + im*2 + ch)
    int slice = blockIdx.x;                // 0..SLICES-1
    int b  = cidx >> 2;
    int im = (cidx >> 1) & 1;
    int ch = cidx & 1;                     // 0 -> g(plane 1), 1 -> b(plane 2)
    const float* src = im ? img_t : img;
    const float4* plane = (const float4*)(src + (size_t)(b * 3 + 1 + ch) * NPIX);

    // 2048 px per slice = 512 float4; 256 threads -> 2 float4 each
    int base = slice * 512;
    #pragma unroll
    for (int v = 0; v < 2; v++) {
        float4 p = plane[base + v * 256 + t];
        process_pixel(p.x, s_a, s_b);
        process_pixel(p.y, s_a, s_b);
        process_pixel(p.z, s_a, s_b);
        process_pixel(p.w, s_a, s_b);
    }
    __syncthreads();

    g_pa[cidx][slice][t] = s_a[t];
    g_pb[cidx][slice][t] = s_b[t];
}

__global__ __launch_bounds__(256) void final_kernel(float* __restrict__ out) {
    int b = blockIdx.x;         // batch 0..7
    int t = threadIdx.x;        // threshold / bin 0..255
    __shared__ float sA[4][NBIN];     // sum sig0 per bin
    __shared__ float sLow[4][NBIN];   // sum sig1 per bin
    __shared__ float sN[4][NBIN];     // counts per bin
    __shared__ float sD[4][NBIN];     // estimated sum(f-1/2) per bin
    __shared__ float H[4][NBIN];
    __shared__ float4 sc4[NBIN];
    __shared__ float red[NBIN];

    // merge phase: thread t handles channel q = t>>6, bins 4*(t&63)..+3
    // channel order q=0..3: g_img, g_img_t, b_img, b_img_t
    {
        int q = t >> 6;
        int j = t & 63;
        int cid_map[4] = { b * 4 + 0, b * 4 + 2, b * 4 + 1, b * 4 + 3 };
        int cid = cid_map[q];
        float4 aa = make_float4(0.f, 0.f, 0.f, 0.f);
        float4 bb = make_float4(0.f, 0.f, 0.f, 0.f);
        #pragma unroll
        for (int sl = 0; sl < SLICES; sl++) {
            float4 va = ((const float4*)g_pa[cid][sl])[j];
            float4 vb = ((const float4*)g_pb[cid][sl])[j];
            aa.x += va.x; aa.y += va.y; aa.z += va.z; aa.w += va.w;
            bb.x += vb.x; bb.y += vb.y; bb.z += vb.z; bb.w += vb.w;
        }
        float av[4] = { aa.x, aa.y, aa.z, aa.w };
        float bv[4] = { bb.x, bb.y, bb.z, bb.w };
        #pragma unroll
        for (int l = 0; l < 4; l++) {
            int bin = 4 * j + l;
            float a = av[l];
            float v = bv[l];                        // 4096*N + sig1-sum (low < 4096)
            float N = floorf(v * (1.0f / 4096.0f));
            sA[q][bin]   = a;
            sLow[q][bin] = v - 4096.0f * N;
            sN[q][bin]   = N;
            sD[q][bin]   = (a - A0_SIG * N) * INV_B0;   // estimated sum(f - 1/2)
        }
    }
    __syncthreads();

    // window reconstruction: H[t] = sig0(bin t) + sig1(bin t-1)
    #pragma unroll
    for (int q = 0; q < 4; q++) {
        float base = sA[q][t];
        if (t >= 1) base += sLow[q][t - 1];
        H[q][t] = base;
    }
    sc4[t] = make_float4(sN[0][t], sN[1][t], sN[2][t], sN[3][t]);
    __syncthreads();

    // tail compensation: threshold t gets A*N[i] + B*D[i] from out-of-window bins i
    {
        float a0 = 0.f, a1 = 0.f, a2 = 0.f, a3 = 0.f;
        #define ACC(IDX, A, B) { int _i = (IDX); if (_i >= 0 && _i < NBIN) { \
            a0 += (A) * sN[0][_i] + (B) * sD[0][_i]; \
            a1 += (A) * sN[1][_i] + (B) * sD[1][_i]; \
            a2 += (A) * sN[2][_i] + (B) * sD[2][_i]; \
            a3 += (A) * sN[3][_i] + (B) * sD[3][_i]; } }
        ACC(t + 1,  A_M1, B1)    // d=-1
        ACC(t - 2,  ET2,  B1)    // d=+2
        ACC(t + 2, -ET3,  B2)    // d=-2 (deficiency vs suffix 1.0)
        ACC(t - 3,  ET3,  B2)    // d=+3
        ACC(t + 3, -ET4,  B3)    // d=-3 (deficiency)
        ACC(t - 4,  ET4,  B3)    // d=+4
        #undef ACC
        H[0][t] += a0; H[1][t] += a1; H[2][t] += a2; H[3][t] += a3;
    }
    __syncthreads();

    // inclusive suffix scan of counts (vectorized over the 4 channels)
    for (int st = 1; st < NBIN; st <<= 1) {
        float4 v = sc4[t];
        if (t + st < NBIN) {
            float4 w = sc4[t + st];
            v.x += w.x; v.y += w.y; v.z += w.z; v.w += w.w;
        }
        __syncthreads();
        sc4[t] = v;
        __syncthreads();
    }

    // + (# pixels with bin >= t+2)
    if (t + 2 < NBIN) {
        float4 suf = sc4[t + 2];
        H[0][t] += suf.x;
        H[1][t] += suf.y;
        H[2][t] += suf.z;
        H[3][t] += suf.w;
    }
    __syncthreads();

    float term = 0.0f;
    if (t < 255) {
        // cdf[J] = (H[0] - H[J+1]) / N ; J = t
        float dg = (H[0][0] - H[0][t + 1]) - (H[1][0] - H[1][t + 1]);
        float db = (H[2][0] - H[2][t + 1]) - (H[3][0] - H[3][t + 1]);
        term = dg * dg + db * db;
    }
    red[t] = term;
    __syncthreads();
    for (int st = 128; st > 0; st >>= 1) {
        if (t < st) red[t] += red[t + st];
        __syncthreads();
    }
    if (t == 0) out[b] = red[0] * (1.0f / (65536.0f * 65536.0f));
}

extern "C" void kernel_launch(void* const* d_in, const int* in_sizes, int n_in,
                              void* d_out, int out_size) {
    const float* img   = (const float*)d_in[0];
    const float* img_t = (const float*)d_in[1];
    float* out = (float*)d_out;

    dim3 grid(SLICES, NCH);
    hist_kernel<<<grid, 256>>>(img, img_t);
    final_kernel<<<8, 256>>>(out);
}

// round 12
// speedup vs baseline: 1.6267x; 1.6267x over previous
#include <cuda_runtime.h>

#define SLICES 32
#define NCH 32            // 8 batches * {img,img_t} * {g,b}
#define NPIX 65536
#define NBIN 256

__device__ float g_pa[NCH][SLICES][NBIN];   // per-CTA sig0 partials (pure d=0 sums)
__device__ float g_pb[NCH][SLICES][NBIN];   // per-CTA fused 4096*N + sig(+1) partials

__device__ __forceinline__ float frcp(float x) {
    float y; asm("rcp.approx.f32 %0, %1;" : "=f"(y) : "f"(x)); return y;
}

#define E_P1 12.182493960703473f       // e^2.5

// sig(2.5f) linear model over f~U[0,1): mean A0, slope b0
#define A0_SIG 0.754354f
#define INV_B0 2.337788f               // 1 / 0.427755

// linear-fit tail compensation: sig(2.5(f-d)) ~= A + B*(f-1/2);  B_d = B_{1-d}
#define A_M1 0.9711630f    // mean of sig(2.5(f+1))      (d=-1)
#define ET2  0.0288370f    // mean of sig(2.5(f-2))      (d=+2)
#define ET3  0.0024650f    // mean of sig(2.5(f-3)); also deficiency at d=-2
#define ET4  0.0002030f    // mean of sig(2.5(f-4)); also deficiency at d=-3
#define B1   0.0639120f    // slope for d=-1 and d=+2
#define B2   0.0056371f    // slope for d=-2 and d=+3
#define B3   0.0004640f    // slope for d=-3 and d=+4

__device__ __forceinline__ void process_pixel(float x, float* s_a, float* s_b) {
    float u = x * 255.0f;
    int k = (int)u;                    // x < 1 -> k <= 254, f in [0,1)
    float f = u - (float)k;
    float e0 = __expf(-2.5f * f);      // e^{-2.5 f}

    atomicAdd(&s_a[k], frcp(1.0f + e0));                    // d=0 -> threshold k
    atomicAdd(&s_b[k], 4096.0f + frcp(1.0f + e0 * E_P1));   // count + d=+1 -> threshold k+1
}

__global__ __launch_bounds__(256) void hist_kernel(const float* __restrict__ img,
                                                   const float* __restrict__ img_t,
                                                   float* __restrict__ out) {
    __shared__ float s_a[NBIN];
    __shared__ float s_b[NBIN];
    int t = threadIdx.x;
    s_a[t] = 0.0f;
    s_b[t] = 0.0f;

    // zero the 8 output slots (pair_kernel accumulates into them; stream order
    // guarantees this store completes before pair_kernel runs)
    if (blockIdx.x == 0 && blockIdx.y == 0 && t < 8) out[t] = 0.0f;
    __syncthreads();

    int cidx = blockIdx.y;                 // 0..31  (= b*4 + im*2 + ch)
    int slice = blockIdx.x;                // 0..SLICES-1
    int b  = cidx >> 2;
    int im = (cidx >> 1) & 1;
    int ch = cidx & 1;                     // 0 -> g(plane 1), 1 -> b(plane 2)
    const float* src = im ? img_t : img;
    const float4* plane = (const float4*)(src + (size_t)(b * 3 + 1 + ch) * NPIX);

    // 2048 px per slice = 512 float4; 256 threads -> 2 float4 each
    int base = slice * 512;
    #pragma unroll
    for (int v = 0; v < 2; v++) {
        float4 p = plane[base + v * 256 + t];
        process_pixel(p.x, s_a, s_b);
        process_pixel(p.y, s_a, s_b);
        process_pixel(p.z, s_a, s_b);
        process_pixel(p.w, s_a, s_b);
    }
    __syncthreads();

    g_pa[cidx][slice][t] = s_a[t];
    g_pb[cidx][slice][t] = s_b[t];
}

// One CTA per (batch, colour) pair: merges img & img_t channels, reconstructs
// histograms, scans, computes sum_t (cdf_x - cdf_y)^2, atomicAdd into out[b].
__global__ __launch_bounds__(256) void pair_kernel(float* __restrict__ out) {
    int bid = blockIdx.x;       // 0..15
    int b  = bid >> 1;          // batch
    int ch = bid & 1;           // 0=g, 1=b
    int t = threadIdx.x;        // 0..255

    __shared__ float sA[2][NBIN];     // sum sig0 per bin
    __shared__ float sLow[2][NBIN];   // sum sig1 per bin
    __shared__ float sN[2][NBIN];     // counts per bin
    __shared__ float sD[2][NBIN];     // estimated sum(f-1/2) per bin
    __shared__ float H[2][NBIN];
    __shared__ float2 sc2[NBIN];
    __shared__ float red[NBIN];

    // merge phase: threads 0-127 -> img channel (c=0), 128-255 -> img_t (c=1);
    // each thread covers 2 bins via float2 loads. 64 float2 loads, high MLP.
    {
        int c = t >> 7;                       // 0: img, 1: img_t
        int j = t & 127;                      // float2 index -> bins 2j, 2j+1
        int cid = b * 4 + c * 2 + ch;         // cidx = b*4 + im*2 + ch
        float2 aa = make_float2(0.f, 0.f);
        float2 bb = make_float2(0.f, 0.f);
        #pragma unroll
        for (int sl = 0; sl < SLICES; sl++) {
            float2 va = ((const float2*)g_pa[cid][sl])[j];
            float2 vb = ((const float2*)g_pb[cid][sl])[j];
            aa.x += va.x; aa.y += va.y;
            bb.x += vb.x; bb.y += vb.y;
        }
        float av[2] = { aa.x, aa.y };
        float bv[2] = { bb.x, bb.y };
        #pragma unroll
        for (int l = 0; l < 2; l++) {
            int bin = 2 * j + l;
            float a = av[l];
            float v = bv[l];                        // 4096*N + sig1-sum (low < 4096)
            float N = floorf(v * (1.0f / 4096.0f));
            sA[c][bin]   = a;
            sLow[c][bin] = v - 4096.0f * N;
            sN[c][bin]   = N;
            sD[c][bin]   = (a - A0_SIG * N) * INV_B0;   // estimated sum(f - 1/2)
        }
    }
    __syncthreads();

    // window reconstruction: H[t] = sig0(bin t) + sig1(bin t-1)
    #pragma unroll
    for (int c = 0; c < 2; c++) {
        float base = sA[c][t];
        if (t >= 1) base += sLow[c][t - 1];
        H[c][t] = base;
    }
    sc2[t] = make_float2(sN[0][t], sN[1][t]);
    __syncthreads();

    // tail compensation: threshold t gets A*N[i] + B*D[i] from out-of-window bins i
    {
        float a0 = 0.f, a1 = 0.f;
        #define ACC(IDX, A, B) { int _i = (IDX); if (_i >= 0 && _i < NBIN) { \
            a0 += (A) * sN[0][_i] + (B) * sD[0][_i]; \
            a1 += (A) * sN[1][_i] + (B) * sD[1][_i]; } }
        ACC(t + 1,  A_M1, B1)    // d=-1
        ACC(t - 2,  ET2,  B1)    // d=+2
        ACC(t + 2, -ET3,  B2)    // d=-2 (deficiency vs suffix 1.0)
        ACC(t - 3,  ET3,  B2)    // d=+3
        ACC(t + 3, -ET4,  B3)    // d=-3 (deficiency)
        ACC(t - 4,  ET4,  B3)    // d=+4
        #undef ACC
        H[0][t] += a0; H[1][t] += a1;
    }
    __syncthreads();

    // inclusive suffix scan of counts (both channels)
    for (int st = 1; st < NBIN; st <<= 1) {
        float2 v = sc2[t];
        if (t + st < NBIN) {
            float2 w = sc2[t + st];
            v.x += w.x; v.y += w.y;
        }
        __syncthreads();
        sc2[t] = v;
        __syncthreads();
    }

    // + (# pixels with bin >= t+2)
    if (t + 2 < NBIN) {
        float2 suf = sc2[t + 2];
        H[0][t] += suf.x;
        H[1][t] += suf.y;
    }
    __syncthreads();

    float term = 0.0f;
    if (t < 255) {
        // cdf[J] = (G[0] - G[J+1]) / N ; dd = cdf_x - cdf_y
        float dd = (H[0][0] - H[0][t + 1]) - (H[1][0] - H[1][t + 1]);
        term = dd * dd;
    }
    red[t] = term;
    __syncthreads();
    for (int st = 128; st > 0; st >>= 1) {
        if (t < st) red[t] += red[t + st];
        __syncthreads();
    }
    // two CTAs (g and b) accumulate into out[b]; with exact-zero init and two
    // commutative fp32 adds the result is order-independent (bit-deterministic).
    if (t == 0) atomicAdd(&out[b], red[0] * (1.0f / (65536.0f * 65536.0f)));
}

extern "C" void kernel_launch(void* const* d_in, const int* in_sizes, int n_in,
                              void* d_out, int out_size) {
    const float* img   = (const float*)d_in[0];
    const float* img_t = (const float*)d_in[1];
    float* out = (float*)d_out;

    dim3 grid(SLICES, NCH);
    hist_kernel<<<grid, 256>>>(img, img_t, out);
    pair_kernel<<<16, 256>>>(out);
}

// round 13
// speedup vs baseline: 1.8243x; 1.1215x over previous
#include <cuda_runtime.h>

#define SLICES 32
#define NCH 32            // 8 batches * {img,img_t} * {g,b}
#define NPIX 65536
#define NBIN 256

__device__ float g_pa[NCH][SLICES][NBIN];   // per-CTA sig0 partials
__device__ float g_pb[NCH][SLICES][NBIN];   // per-CTA fused 4096*N + sig(+1) partials
__device__ float g_mA[NCH][NBIN];           // merged sig0 sums
__device__ float g_mB[NCH][NBIN];           // merged encoded sums

__device__ __forceinline__ float frcp(float x) {
    float y; asm("rcp.approx.f32 %0, %1;" : "=f"(y) : "f"(x)); return y;
}

#define E_P1 12.182493960703473f       // e^2.5

// sig(2.5f) linear model over f~U[0,1): mean A0, slope b0
#define A0_SIG 0.754354f
#define INV_B0 2.337788f               // 1 / 0.427755

// linear-fit tail compensation: sig(2.5(f-d)) ~= A + B*(f-1/2);  B_d = B_{1-d}
#define A_M1 0.9711630f    // mean of sig(2.5(f+1))      (d=-1)
#define ET2  0.0288370f    // mean of sig(2.5(f-2))      (d=+2)
#define ET3  0.0024650f    // mean of sig(2.5(f-3)); also deficiency at d=-2
#define ET4  0.0002030f    // mean of sig(2.5(f-4)); also deficiency at d=-3
#define B1   0.0639120f    // slope for d=-1 and d=+2
#define B2   0.0056371f    // slope for d=-2 and d=+3
#define B3   0.0004640f    // slope for d=-3 and d=+4

__device__ __forceinline__ void process_pixel(float x, float* s_a, float* s_b) {
    float u = x * 255.0f;
    int k = (int)u;                    // x < 1 -> k <= 254, f in [0,1)
    float f = u - (float)k;
    float e0 = __expf(-2.5f * f);      // e^{-2.5 f}

    atomicAdd(&s_a[k], frcp(1.0f + e0));                    // d=0 -> threshold k
    atomicAdd(&s_b[k], 4096.0f + frcp(1.0f + e0 * E_P1));   // count + d=+1 -> threshold k+1
}

__global__ __launch_bounds__(256) void hist_kernel(const float* __restrict__ img,
                                                   const float* __restrict__ img_t,
                                                   float* __restrict__ out) {
    __shared__ float s_a[NBIN];
    __shared__ float s_b[NBIN];
    int t = threadIdx.x;
    s_a[t] = 0.0f;
    s_b[t] = 0.0f;

    // zero the 8 output slots (pair_kernel accumulates into them)
    if (blockIdx.x == 0 && blockIdx.y == 0 && t < 8) out[t] = 0.0f;
    __syncthreads();

    int cidx = blockIdx.y;                 // 0..31  (= b*4 + im*2 + ch)
    int slice = blockIdx.x;                // 0..SLICES-1
    int b  = cidx >> 2;
    int im = (cidx >> 1) & 1;
    int ch = cidx & 1;                     // 0 -> g(plane 1), 1 -> b(plane 2)
    const float* src = im ? img_t : img;
    const float4* plane = (const float4*)(src + (size_t)(b * 3 + 1 + ch) * NPIX);

    int base = slice * 512;
    #pragma unroll
    for (int v = 0; v < 2; v++) {
        float4 p = plane[base + v * 256 + t];
        process_pixel(p.x, s_a, s_b);
        process_pixel(p.y, s_a, s_b);
        process_pixel(p.z, s_a, s_b);
        process_pixel(p.w, s_a, s_b);
    }
    __syncthreads();

    g_pa[cidx][slice][t] = s_a[t];
    g_pb[cidx][slice][t] = s_b[t];
}

// 64 CTAs: blockIdx.x = array (0:A, 1:B), blockIdx.y = channel.
// Thread t sums 32 slice partials (independent loads, high MLP).
__global__ __launch_bounds__(256) void mid_kernel() {
    int c = blockIdx.y;
    int t = threadIdx.x;
    const float* src = blockIdx.x ? &g_pb[c][0][0] : &g_pa[c][0][0];
    float* dst = blockIdx.x ? &g_mB[c][0] : &g_mA[c][0];
    float acc0 = 0.f, acc1 = 0.f, acc2 = 0.f, acc3 = 0.f;
    #pragma unroll
    for (int sl = 0; sl < SLICES; sl += 4) {
        acc0 += src[(sl + 0) * NBIN + t];
        acc1 += src[(sl + 1) * NBIN + t];
        acc2 += src[(sl + 2) * NBIN + t];
        acc3 += src[(sl + 3) * NBIN + t];
    }
    dst[t] = (acc0 + acc1) + (acc2 + acc3);
}

// One CTA per (batch, colour) pair: reads merged arrays, reconstructs
// histograms, scans (warp shuffles), computes sum_t (cdf_x-cdf_y)^2.
__global__ __launch_bounds__(256) void pair_kernel(float* __restrict__ out) {
    int bid = blockIdx.x;       // 0..15
    int b  = bid >> 1;          // batch
    int ch = bid & 1;           // 0=g, 1=b
    int t = threadIdx.x;        // 0..255
    int lane = t & 31;
    int wid = t >> 5;

    __shared__ float sN[2][NBIN];
    __shared__ float sD[2][NBIN];
    __shared__ float sW[2][NBIN];     // window hist contribution pieces
    __shared__ float H[2][NBIN];
    __shared__ float scs[2][NBIN];    // scanned counts
    __shared__ float wtot[2][8];      // per-warp suffix totals
    __shared__ float wred[8];

    // load + decode both channels (c=0: img, c=1: img_t)
    #pragma unroll
    for (int c = 0; c < 2; c++) {
        int cid = b * 4 + c * 2 + ch;
        float a = g_mA[cid][t];
        float v = g_mB[cid][t];
        float N = floorf(v * (1.0f / 4096.0f));
        float low = v - 4096.0f * N;          // sum sig1 of bin t
        sN[c][t] = N;
        sD[c][t] = (a - A0_SIG * N) * INV_B0;
        sW[c][t] = low;                        // sig1 part (goes to threshold t+1)
        H[c][t] = a;                           // sig0 part (threshold t)
    }
    __syncthreads();

    // window reconstruction + tail compensation
    #pragma unroll
    for (int c = 0; c < 2; c++) {
        float acc = H[c][t];
        if (t >= 1) acc += sW[c][t - 1];
        #define ACC(IDX, A, B) { int _i = (IDX); if (_i >= 0 && _i < NBIN) \
            acc += (A) * sN[c][_i] + (B) * sD[c][_i]; }
        ACC(t + 1,  A_M1, B1)    // d=-1
        ACC(t - 2,  ET2,  B1)    // d=+2
        ACC(t + 2, -ET3,  B2)    // d=-2 (deficiency vs suffix 1.0)
        ACC(t - 3,  ET3,  B2)    // d=+3
        ACC(t + 3, -ET4,  B3)    // d=-3 (deficiency)
        ACC(t - 4,  ET4,  B3)    // d=+4
        #undef ACC
        H[c][t] = acc;
    }

    // suffix scan of counts via warp shuffles (inclusive, descending index)
    #pragma unroll
    for (int c = 0; c < 2; c++) {
        float v = sN[c][t];
        #pragma unroll
        for (int off = 1; off < 32; off <<= 1) {
            float w = __shfl_down_sync(0xFFFFFFFFu, v, off);
            if (lane + off < 32) v += w;
        }
        // v now = suffix sum within warp; lane 0 holds the warp total
        if (lane == 0) wtot[c][wid] = v;
        scs[c][t] = v;
    }
    __syncthreads();
    #pragma unroll
    for (int c = 0; c < 2; c++) {
        float add = 0.f;
        for (int w = wid + 1; w < 8; w++) add += wtot[c][w];
        scs[c][t] += add;
    }
    __syncthreads();

    // + (# pixels with bin >= t+2)
    #pragma unroll
    for (int c = 0; c < 2; c++) {
        if (t + 2 < NBIN) H[c][t] += scs[c][t + 2];
    }
    __syncthreads();

    float term = 0.0f;
    if (t < 255) {
        float dd = (H[0][0] - H[0][t + 1]) - (H[1][0] - H[1][t + 1]);
        term = dd * dd;
    }
    // block reduction via shuffles
    #pragma unroll
    for (int off = 16; off > 0; off >>= 1)
        term += __shfl_down_sync(0xFFFFFFFFu, term, off);
    if (lane == 0) wred[wid] = term;
    __syncthreads();
    if (wid == 0) {
        float v = (lane < 8) ? wred[lane] : 0.0f;
        #pragma unroll
        for (int off = 4; off > 0; off >>= 1)
            v += __shfl_down_sync(0xFFFFFFFFu, v, off);
        // two CTAs (g and b) accumulate into out[b]; exact-zero init + two
        // commutative fp32 adds -> order-independent result.
        if (lane == 0) atomicAdd(&out[b], v * (1.0f / (65536.0f * 65536.0f)));
    }
}

extern "C" void kernel_launch(void* const* d_in, const int* in_sizes, int n_in,
                              void* d_out, int out_size) {
    const float* img   = (const float*)d_in[0];
    const float* img_t = (const float*)d_in[1];
    float* out = (float*)d_out;

    dim3 grid(SLICES, NCH);
    hist_kernel<<<grid, 256>>>(img, img_t, out);
    dim3 mgrid(2, NCH);
    mid_kernel<<<mgrid, 256>>>();
    pair_kernel<<<16, 256>>>(out);
}